// round 6
// baseline (speedup 1.0000x reference)
#include <cuda_runtime.h>
#include <cstdint>

#define T_BATCH 256
#define D_IN    784
#define M_      800
#define N_      8
#define K_      25
#define MN_     6400
#define ROW_BYTES (MN_ * 4)
#define NEG_INF (-3.402823466e38f)

// Scratch (allocation-free rule: __device__ globals)
__device__ float g_WbT[(size_t)MN_ * MN_];   // W_b transposed (163.84 MB)
__device__ float g_A[T_BATCH * M_];          // A[t][m] = W_a @ x_t + b_a
__device__ float g_WdT[M_ * D_IN];           // W_d transposed

// Monotone float<->uint order mapping (no NaNs in this workload)
__device__ __forceinline__ unsigned fmap(unsigned b) {
    return (b & 0x80000000u) ? ~b : (b | 0x80000000u);
}
__device__ __forceinline__ float funmap(unsigned u) {
    unsigned b = (u & 0x80000000u) ? (u & 0x7FFFFFFFu) : ~u;
    return __uint_as_float(b);
}

__device__ __forceinline__ uint32_t smem_u32(const void* p) {
    uint32_t a;
    asm("{ .reg .u64 t; cvta.to.shared.u64 t, %1; cvt.u32.u64 %0, t; }"
        : "=r"(a) : "l"(p));
    return a;
}

__device__ __forceinline__ void mbar_wait(uint32_t mbar, unsigned parity) {
    asm volatile(
        "{\n\t.reg .pred P;\n"
        "W%=:\n\t"
        "mbarrier.try_wait.parity.acquire.cta.shared::cta.b64 P, [%0], %1;\n\t"
        "@!P bra W%=;\n\t}"
        :: "r"(mbar), "r"(parity) : "memory");
}

// ---------------------------------------------------------------------------
// Mega prep kernel, 256 threads/block:
//   blocks [0,200)      : A = X @ Wa^T + ba   (32x32 tiles, 2x2 micro-tiles)
//   blocks [200,825)    : W_d transpose (784,800) -> (800,784)
//   blocks [825,40825)  : W_b transpose 6400x6400 (DRAM-bound; overlaps GEMM)
// ---------------------------------------------------------------------------
#define GEMM_BLKS 200
#define WD_BLKS   625
#define WB_BASE   (GEMM_BLKS + WD_BLKS)
#define PREP_BLKS (WB_BASE + 200 * 200)
#define TS 36   // 144B row stride: 16B-aligned rows for float4 LDS/STS

__global__ void __launch_bounds__(256)
prep_kernel(const float* __restrict__ X, const float* __restrict__ Wa,
            const float* __restrict__ ba, const float* __restrict__ Wd,
            const float* __restrict__ Wb) {
    __shared__ __align__(16) float sh[2 * 32 * TS];
    const int b = blockIdx.x;
    const int tid = threadIdx.x;

    if (b >= WB_BASE) {
        float (*tile)[33] = (float(*)[33])sh;
        int b2 = b - WB_BASE;
        int bx = b2 % 200, by = b2 / 200;
        int tx = tid & 31, ty = tid >> 5;
        int x = bx * 32 + tx;
        int y0 = by * 32;
#pragma unroll
        for (int i = ty; i < 32; i += 8)
            tile[i][tx] = Wb[(size_t)(y0 + i) * MN_ + x];
        __syncthreads();
        int x2 = by * 32 + tx;
        int y2 = bx * 32;
#pragma unroll
        for (int i = ty; i < 32; i += 8)
            g_WbT[(size_t)(y2 + i) * MN_ + x2] = tile[tx][i];
    } else if (b < GEMM_BLKS) {
        float (*Xs)[TS] = (float(*)[TS])sh;
        float (*Ws)[TS] = (float(*)[TS])(sh + 32 * TS);
        const int bm = b % 25, bt = b / 25;
        const int lrow = tid >> 3, lc4 = tid & 7;
        const int tx = tid & 15, ty = tid >> 4;
        float c00 = 0.f, c01 = 0.f, c10 = 0.f, c11 = 0.f;
        for (int k0 = 0; k0 < D_IN; k0 += 32) {
            int kc = k0 + lc4 * 4;
            float4 xv = (kc + 3 < D_IN)
                ? *(const float4*)(X + (bt * 32 + lrow) * D_IN + kc)
                : make_float4(0.f, 0.f, 0.f, 0.f);
            float4 wv = (kc + 3 < D_IN)
                ? *(const float4*)(Wa + (bm * 32 + lrow) * D_IN + kc)
                : make_float4(0.f, 0.f, 0.f, 0.f);
            __syncthreads();
            *(float4*)&Xs[lrow][lc4 * 4] = xv;
            *(float4*)&Ws[lrow][lc4 * 4] = wv;
            __syncthreads();
#pragma unroll
            for (int k = 0; k < 32; k += 4) {
                float4 x0 = *(const float4*)&Xs[2 * ty][k];
                float4 x1 = *(const float4*)&Xs[2 * ty + 1][k];
                float4 w0 = *(const float4*)&Ws[2 * tx][k];
                float4 w1 = *(const float4*)&Ws[2 * tx + 1][k];
                c00 = fmaf(x0.x, w0.x, c00); c00 = fmaf(x0.y, w0.y, c00);
                c00 = fmaf(x0.z, w0.z, c00); c00 = fmaf(x0.w, w0.w, c00);
                c01 = fmaf(x0.x, w1.x, c01); c01 = fmaf(x0.y, w1.y, c01);
                c01 = fmaf(x0.z, w1.z, c01); c01 = fmaf(x0.w, w1.w, c01);
                c10 = fmaf(x1.x, w0.x, c10); c10 = fmaf(x1.y, w0.y, c10);
                c10 = fmaf(x1.z, w0.z, c10); c10 = fmaf(x1.w, w0.w, c10);
                c11 = fmaf(x1.x, w1.x, c11); c11 = fmaf(x1.y, w1.y, c11);
                c11 = fmaf(x1.z, w1.z, c11); c11 = fmaf(x1.w, w1.w, c11);
            }
        }
        int m0 = bm * 32 + 2 * tx, t0 = bt * 32 + 2 * ty;
        g_A[t0 * M_ + m0]           = c00 + ba[m0];
        g_A[t0 * M_ + m0 + 1]       = c01 + ba[m0 + 1];
        g_A[(t0 + 1) * M_ + m0]     = c10 + ba[m0];
        g_A[(t0 + 1) * M_ + m0 + 1] = c11 + ba[m0 + 1];
    } else {
        float (*tile)[33] = (float(*)[33])sh;
        int r = b - GEMM_BLKS;
        int g0 = (r % 25) * 32;
        int d0 = (r / 25) * 32;
        int tx = tid & 31, ty = tid >> 5;
#pragma unroll
        for (int i = ty; i < 32; i += 8) {
            int d = d0 + i, g = g0 + tx;
            if (d < D_IN) tile[i][tx] = Wd[d * M_ + g];
        }
        __syncthreads();
#pragma unroll
        for (int i = ty; i < 32; i += 8) {
            int g = g0 + i, d = d0 + tx;
            if (d < D_IN) g_WdT[g * D_IN + d] = tile[tx][i];
        }
    }
}

// ---------------------------------------------------------------------------
// Main sequential scan: single CTA, 800 threads (thread m owns group 8m..8m+7).
// W column arrives via cp.async.bulk into smem (issued mid-scalar-resolve,
// consumed next step after mbarrier wait). No sigma array in smem — all
// arbitrary-index sigma reads are derived from the reductions.
// ---------------------------------------------------------------------------
__global__ void __launch_bounds__(800, 1)
scan_kernel(const float* __restrict__ bb, const float* __restrict__ bd,
            float* __restrict__ out) {
    __shared__ __align__(128) float wbuf[MN_];    // 25.6 KB TMA landing buffer
    __shared__ float lam_s[M_];                   // group max sigma excl jp
    __shared__ unsigned red_u[25], red_j[25], red_m[25];
    __shared__ float s_smin, s_sj, s_sigjp;
    __shared__ int   s_jstar;
    __shared__ __align__(8) unsigned long long s_mbar;

    const int tid  = threadIdx.x;
    const int lane = tid & 31;
    const int wid  = tid >> 5;
    const uint32_t mbar = smem_u32(&s_mbar);
    const uint32_t wdst = smem_u32(wbuf);

    if (tid == 0)
        asm volatile("mbarrier.init.shared.b64 [%0], 1;" :: "r"(mbar) : "memory");
    // Zero the x_b / phi / psi tail (d_out is poisoned)
    for (int i = tid; i < 3 * MN_; i += 800) out[T_BATCH * D_IN + i] = 0.0f;
    __syncthreads();

    // Per-thread constants
    const float4* bb4 = (const float4*)bb;
    const float4 bbA = bb4[2 * tid];
    const float4 bbB = bb4[2 * tid + 1];
    const int aoff = 8 * (tid % 100);      // (8*tid) % 800, float4-aligned
    const float bdv = (tid < D_IN) ? bd[tid] : 0.0f;

    int   jp   = -1;     // active one-hot index of x_b / phi (-1 = zero vectors)
    float phiv = 0.0f;   // phi value at jp
    float4 aA = *(const float4*)(g_A + aoff);    // prefetched A row
    float4 aB = *(const float4*)(g_A + aoff + 4);

    for (int t = 0; t < T_BATCH; ++t) {
        const bool use = (jp >= 0);
        if (t > 0 && use)
            mbar_wait(mbar, (unsigned)((t & 1) ^ 1));   // completion #(t-1)
        else if (t > 1)
            mbar_wait(mbar, (unsigned)((t & 1) ^ 1));   // keep phase bookkeeping exact

        // sigma = tile(a,N) + W_b[:,jp] + b_b   (reference add order)
        float s[8];
        if (use) {
            float4 wA = ((const float4*)wbuf)[2 * tid];
            float4 wB = ((const float4*)wbuf)[2 * tid + 1];
            s[0] = (aA.x + wA.x) + bbA.x;  s[1] = (aA.y + wA.y) + bbA.y;
            s[2] = (aA.z + wA.z) + bbA.z;  s[3] = (aA.w + wA.w) + bbA.w;
            s[4] = (aB.x + wB.x) + bbB.x;  s[5] = (aB.y + wB.y) + bbB.y;
            s[6] = (aB.z + wB.z) + bbB.z;  s[7] = (aB.w + wB.w) + bbB.w;
        } else {
            s[0] = aA.x + bbA.x;  s[1] = aA.y + bbA.y;
            s[2] = aA.z + bbA.z;  s[3] = aA.w + bbA.w;
            s[4] = aB.x + bbB.x;  s[5] = aB.y + bbB.y;
            s[6] = aB.z + bbB.z;  s[7] = aB.w + bbB.w;
        }

        // Owner of jp publishes sigma[jp] (single arbitrary-index value needed)
        if (use && tid == (jp >> 3)) s_sigjp = s[jp & 7];

        // Thread-local reductions: global min, argmax excl jp (first-index
        // ties), group max excl jp (lam)
        unsigned um = 0xFFFFFFFFu, bu = 0u, bj = 0u;
        float gm = NEG_INF;
#pragma unroll
        for (int i = 0; i < 8; ++i) {
            unsigned u = fmap(__float_as_uint(s[i]));
            um = min(um, u);
            int j = 8 * tid + i;
            if (j != jp) {
                if (u > bu) { bu = u; bj = (unsigned)j; }
                gm = fmaxf(gm, s[i]);
            }
        }
        lam_s[tid] = gm;
        unsigned wu = __reduce_max_sync(0xFFFFFFFFu, bu);
        unsigned wj = __reduce_min_sync(0xFFFFFFFFu, (bu == wu) ? bj : 0xFFFFFFFFu);
        unsigned wm = __reduce_min_sync(0xFFFFFFFFu, um);
        if (lane == 0) { red_u[wid] = wu; red_j[wid] = wj; red_m[wid] = wm; }
        __syncthreads();                                       // bar1
        if (wid == 0) {
            const bool v = (lane < 25);
            unsigned ru = v ? red_u[lane] : 0u;
            unsigned rj = v ? red_j[lane] : 0xFFFFFFFFu;
            unsigned rm = v ? red_m[lane] : 0xFFFFFFFFu;
            unsigned gu  = __reduce_max_sync(0xFFFFFFFFu, ru);
            unsigned gj  = __reduce_min_sync(0xFFFFFFFFu, (ru == gu) ? rj : 0xFFFFFFFFu);
            unsigned gmn = __reduce_min_sync(0xFFFFFFFFu, rm);
            if (lane == 0) {
                float smin = funmap(gmn);
                float vM1  = funmap(gu);     // sigma[M1], bit-exact
                int M1 = (int)gj;
                int jstar = M1;
                float sj  = vM1;
                if (jp >= 0) {
                    float sigjp = s_sigjp;
                    float v1 = (vM1 - smin) + 1.0f;
                    float pv = (1.0f - phiv) * ((sigjp - smin) + 1.0f);
                    if (pv > v1 || (pv == v1 && jp < M1)) { jstar = jp; sj = sigjp; }
                }
                s_smin  = smin;
                s_jstar = jstar;
                s_sj    = sj;
                // Issue next W-column bulk copy NOW (max overlap window).
                // Skip on last step: no in-flight async writes at exit.
                if (t + 1 < T_BATCH) {
                    asm volatile("fence.proxy.async.shared::cta;" ::: "memory");
                    asm volatile(
                        "mbarrier.arrive.expect_tx.shared.b64 _, [%0], %1;"
                        :: "r"(mbar), "r"((unsigned)ROW_BYTES) : "memory");
                    const void* src = (const void*)(g_WbT + (size_t)jstar * MN_);
                    asm volatile(
                        "cp.async.bulk.shared::cta.global.mbarrier::complete_tx::bytes "
                        "[%0], [%1], %2, [%3];"
                        :: "r"(wdst), "l"(src), "r"((unsigned)ROW_BYTES), "r"(mbar)
                        : "memory");
                }
            }
        }
        __syncthreads();                                       // bar2
        const float smin  = s_smin;
        const int   jstar = s_jstar;
        const float sj    = s_sj;
        const int   q     = jstar % M_;      // tile-group gating index
        const int   gp    = (jp >= 0) ? (jp >> 3) : -1;

        // Prefetch next A row + W_d column (overlap rank phase)
        {
            int tn = (t + 1 < T_BATCH) ? t + 1 : 0;
            const float* ar = g_A + tn * M_;
            aA = *(const float4*)(ar + aoff);
            aB = *(const float4*)(ar + aoff + 4);
        }
        const float wd = (tid < D_IN) ? g_WdT[(jstar >> 3) * D_IN + tid] : 0.0f;

        // Rank of q among lam (stable top-k semantics), pi-space
        float pvp = 0.0f;
        if (jp >= 0) pvp = (1.0f - phiv) * ((s_sigjp - smin) + 1.0f);
        float lamq = (lam_s[q] - smin) + 1.0f;
        if (q == gp) lamq = fmaxf(lamq, pvp);
        int flag = 0;
        if (tid != q) {
            float lm = (gm - smin) + 1.0f;
            if (tid == gp) lm = fmaxf(lm, pvp);
            flag = (lm > lamq) || (lm == lamq && tid < q);
        }
        const int cnt = __syncthreads_count(flag);             // bar3

        const float tt   = tanhf(sj);
        const float yval = (cnt < K_) ? tt : 0.0f;             // m_lam gate
        const float gval = (yval > 0.0f) ? yval : 0.0f;

        if (tid < D_IN)
            out[t * D_IN + tid] = (gval > 0.0f) ? fmaf(wd, gval, bdv) : bdv;

        if (yval > 0.0f) { jp = jstar; phiv = yval; }
        else             { jp = -1;    phiv = 0.0f; }
    }

    // Final outputs: x_b (exactly one-hot 1.0), phi, psis[-1]
    if (tid == 0 && jp >= 0) {
        out[T_BATCH * D_IN + jp]           = 1.0f;   // x_b
        out[T_BATCH * D_IN + MN_ + jp]     = phiv;   // phi
        out[T_BATCH * D_IN + 2 * MN_ + jp] = phiv;   // psis[-1]
    }
}

// ---------------------------------------------------------------------------
extern "C" void kernel_launch(void* const* d_in, const int* in_sizes, int n_in,
                              void* d_out, int out_size) {
    const float* X  = (const float*)d_in[0];
    const float* Wa = (const float*)d_in[1];
    const float* ba = (const float*)d_in[2];
    const float* Wb = (const float*)d_in[3];
    const float* bb = (const float*)d_in[4];
    const float* Wd = (const float*)d_in[5];
    const float* bd = (const float*)d_in[6];
    float* out = (float*)d_out;

    prep_kernel<<<PREP_BLKS, 256>>>(X, Wa, ba, Wd, Wb);
    scan_kernel<<<1, 800>>>(bb, bd, out);
}

// round 10
// speedup vs baseline: 1.0871x; 1.0871x over previous
#include <cuda_runtime.h>
#include <cstdint>

#define T_BATCH 256
#define D_IN    784
#define M_      800
#define N_      8
#define K_      25
#define MN_     6400
#define NEG_INF (-3.402823466e38f)

// Scratch (allocation-free rule: __device__ globals)
__device__ float g_WbT[(size_t)MN_ * MN_];   // W_b transposed (163.84 MB)
__device__ float g_A[T_BATCH * M_];          // A[t][m] = W_a @ x_t + b_a
__device__ float g_WdT[M_ * D_IN];           // W_d transposed

// Monotone float<->uint order mapping (no NaNs in this workload)
__device__ __forceinline__ unsigned fmap(unsigned b) {
    return (b & 0x80000000u) ? ~b : (b | 0x80000000u);
}
__device__ __forceinline__ float funmap(unsigned u) {
    unsigned b = (u & 0x80000000u) ? (u & 0x7FFFFFFFu) : ~u;
    return __uint_as_float(b);
}

// ---------------------------------------------------------------------------
// Mega prep kernel (unchanged from R5; ~29us measured)
// ---------------------------------------------------------------------------
#define GEMM_BLKS 200
#define WD_BLKS   625
#define WB_BASE   (GEMM_BLKS + WD_BLKS)
#define PREP_BLKS (WB_BASE + 200 * 200)
#define TS 36   // 144B row stride: 16B-aligned rows for float4 LDS/STS

__global__ void __launch_bounds__(256)
prep_kernel(const float* __restrict__ X, const float* __restrict__ Wa,
            const float* __restrict__ ba, const float* __restrict__ Wd,
            const float* __restrict__ Wb) {
    __shared__ __align__(16) float sh[2 * 32 * TS];
    const int b = blockIdx.x;
    const int tid = threadIdx.x;

    if (b >= WB_BASE) {
        float (*tile)[33] = (float(*)[33])sh;
        int b2 = b - WB_BASE;
        int bx = b2 % 200, by = b2 / 200;
        int tx = tid & 31, ty = tid >> 5;
        int x = bx * 32 + tx;
        int y0 = by * 32;
#pragma unroll
        for (int i = ty; i < 32; i += 8)
            tile[i][tx] = Wb[(size_t)(y0 + i) * MN_ + x];
        __syncthreads();
        int x2 = by * 32 + tx;
        int y2 = bx * 32;
#pragma unroll
        for (int i = ty; i < 32; i += 8)
            g_WbT[(size_t)(y2 + i) * MN_ + x2] = tile[tx][i];
    } else if (b < GEMM_BLKS) {
        float (*Xs)[TS] = (float(*)[TS])sh;
        float (*Ws)[TS] = (float(*)[TS])(sh + 32 * TS);
        const int bm = b % 25, bt = b / 25;
        const int lrow = tid >> 3, lc4 = tid & 7;
        const int tx = tid & 15, ty = tid >> 4;
        float c00 = 0.f, c01 = 0.f, c10 = 0.f, c11 = 0.f;
        for (int k0 = 0; k0 < D_IN; k0 += 32) {
            int kc = k0 + lc4 * 4;
            float4 xv = (kc + 3 < D_IN)
                ? *(const float4*)(X + (bt * 32 + lrow) * D_IN + kc)
                : make_float4(0.f, 0.f, 0.f, 0.f);
            float4 wv = (kc + 3 < D_IN)
                ? *(const float4*)(Wa + (bm * 32 + lrow) * D_IN + kc)
                : make_float4(0.f, 0.f, 0.f, 0.f);
            __syncthreads();
            *(float4*)&Xs[lrow][lc4 * 4] = xv;
            *(float4*)&Ws[lrow][lc4 * 4] = wv;
            __syncthreads();
#pragma unroll
            for (int k = 0; k < 32; k += 4) {
                float4 x0 = *(const float4*)&Xs[2 * ty][k];
                float4 x1 = *(const float4*)&Xs[2 * ty + 1][k];
                float4 w0 = *(const float4*)&Ws[2 * tx][k];
                float4 w1 = *(const float4*)&Ws[2 * tx + 1][k];
                c00 = fmaf(x0.x, w0.x, c00); c00 = fmaf(x0.y, w0.y, c00);
                c00 = fmaf(x0.z, w0.z, c00); c00 = fmaf(x0.w, w0.w, c00);
                c01 = fmaf(x0.x, w1.x, c01); c01 = fmaf(x0.y, w1.y, c01);
                c01 = fmaf(x0.z, w1.z, c01); c01 = fmaf(x0.w, w1.w, c01);
                c10 = fmaf(x1.x, w0.x, c10); c10 = fmaf(x1.y, w0.y, c10);
                c10 = fmaf(x1.z, w0.z, c10); c10 = fmaf(x1.w, w0.w, c10);
                c11 = fmaf(x1.x, w1.x, c11); c11 = fmaf(x1.y, w1.y, c11);
                c11 = fmaf(x1.z, w1.z, c11); c11 = fmaf(x1.w, w1.w, c11);
            }
        }
        int m0 = bm * 32 + 2 * tx, t0 = bt * 32 + 2 * ty;
        g_A[t0 * M_ + m0]           = c00 + ba[m0];
        g_A[t0 * M_ + m0 + 1]       = c01 + ba[m0 + 1];
        g_A[(t0 + 1) * M_ + m0]     = c10 + ba[m0];
        g_A[(t0 + 1) * M_ + m0 + 1] = c11 + ba[m0 + 1];
    } else {
        float (*tile)[33] = (float(*)[33])sh;
        int r = b - GEMM_BLKS;
        int g0 = (r % 25) * 32;
        int d0 = (r / 25) * 32;
        int tx = tid & 31, ty = tid >> 5;
#pragma unroll
        for (int i = ty; i < 32; i += 8) {
            int d = d0 + i, g = g0 + tx;
            if (d < D_IN) tile[i][tx] = Wd[d * M_ + g];
        }
        __syncthreads();
#pragma unroll
        for (int i = ty; i < 32; i += 8) {
            int g = g0 + i, d = d0 + tx;
            if (d < D_IN) g_WdT[g * D_IN + d] = tile[tx][i];
        }
    }
}

// ---------------------------------------------------------------------------
// Main sequential scan: single CTA, 800 threads.
// Thread tid owns float4 chunks f=tid (j=4tid..4tid+3, reshape-group tid>>1)
// and f=tid+800 (j=3200+4tid.., group 400+(tid>>1)) -> fully COALESCED
// W-column and A-row loads. Group-of-8 maxes rebuilt via shfl_xor(1).
// Both chunks share the same tiled-a values (3200 % 800 == 0) -> one A load.
// ---------------------------------------------------------------------------
__global__ void __launch_bounds__(800, 1)
scan_kernel(const float* __restrict__ bb, const float* __restrict__ bd,
            float* __restrict__ out) {
    __shared__ float lam_s[M_];                   // group max sigma excl jp
    __shared__ unsigned red_u[25], red_j[25], red_m[25];
    __shared__ float s_smin, s_sj, s_sigjp;
    __shared__ int   s_jstar;

    const int tid  = threadIdx.x;
    const int lane = tid & 31;
    const int wid  = tid >> 5;

    // Zero the x_b / phi / psi tail (d_out is poisoned)
    for (int i = tid; i < 3 * MN_; i += 800) out[T_BATCH * D_IN + i] = 0.0f;
    __syncthreads();

    // Per-thread constants
    const float4* bb4 = (const float4*)bb;
    const float4 bbA = bb4[tid];
    const float4 bbB = bb4[tid + 800];
    const int aoff = 4 * (tid % 200);      // a-index for BOTH chunks
    const float bdv = (tid < D_IN) ? bd[tid] : 0.0f;
    const int jA0 = 4 * tid;               // first j of chunk A
    const int jB0 = 3200 + 4 * tid;        // first j of chunk B
    const int mA  = tid >> 1;              // reshape group of chunk A
    const int mB  = 400 + (tid >> 1);      // reshape group of chunk B
    const bool even = (tid & 1) == 0;

    int   jp   = -1;     // active one-hot index of x_b / phi (-1 = zero vectors)
    float phiv = 0.0f;   // phi value at jp
    float4 cA = make_float4(0.f, 0.f, 0.f, 0.f);   // prefetched W column
    float4 cB = make_float4(0.f, 0.f, 0.f, 0.f);
    float4 aV = *(const float4*)(g_A + aoff);       // A row 0

    for (int t = 0; t < T_BATCH; ++t) {
        // Issue next A row load immediately (address known; full-step overlap)
        const int tn = (t + 1 < T_BATCH) ? t + 1 : 0;
        const float4 aNext = *(const float4*)(g_A + tn * M_ + aoff);

        const bool use = (jp >= 0);
        // sigma = tile(a,N) + W_b[:,jp] + b_b   (reference add order)
        float s[8];
        s[0] = (aV.x + (use ? cA.x : 0.f)) + bbA.x;
        s[1] = (aV.y + (use ? cA.y : 0.f)) + bbA.y;
        s[2] = (aV.z + (use ? cA.z : 0.f)) + bbA.z;
        s[3] = (aV.w + (use ? cA.w : 0.f)) + bbA.w;
        s[4] = (aV.x + (use ? cB.x : 0.f)) + bbB.x;
        s[5] = (aV.y + (use ? cB.y : 0.f)) + bbB.y;
        s[6] = (aV.z + (use ? cB.z : 0.f)) + bbB.z;
        s[7] = (aV.w + (use ? cB.w : 0.f)) + bbB.w;

        // Owner of jp publishes sigma[jp]
        if (use) {
            int f = jp >> 2;
            int owner = (f < 800) ? f : f - 800;
            if (tid == owner) s_sigjp = s[(jp & 3) + ((f < 800) ? 0 : 4)];
        }

        // Thread-local reductions: global min, argmax excl jp (first-index
        // ties), per-chunk group max excl jp
        unsigned um = 0xFFFFFFFFu, bu = 0u, bj = 0u;
        float gmA = NEG_INF, gmB = NEG_INF;
#pragma unroll
        for (int i = 0; i < 4; ++i) {
            unsigned u = fmap(__float_as_uint(s[i]));
            um = min(um, u);
            int j = jA0 + i;
            if (j != jp) {
                if (u > bu) { bu = u; bj = (unsigned)j; }
                gmA = fmaxf(gmA, s[i]);
            }
        }
#pragma unroll
        for (int i = 0; i < 4; ++i) {
            unsigned u = fmap(__float_as_uint(s[4 + i]));
            um = min(um, u);
            int j = jB0 + i;
            if (j != jp) {
                if (u > bu) { bu = u; bj = (unsigned)j; }
                gmB = fmaxf(gmB, s[4 + i]);
            }
        }
        // Pair-combine half-group maxes (tid, tid^1 share a group per chunk)
        gmA = fmaxf(gmA, __shfl_xor_sync(0xFFFFFFFFu, gmA, 1));
        gmB = fmaxf(gmB, __shfl_xor_sync(0xFFFFFFFFu, gmB, 1));
        if (even) lam_s[mA] = gmA;
        else      lam_s[mB] = gmB;

        unsigned wu = __reduce_max_sync(0xFFFFFFFFu, bu);
        unsigned wj = __reduce_min_sync(0xFFFFFFFFu, (bu == wu) ? bj : 0xFFFFFFFFu);
        unsigned wm = __reduce_min_sync(0xFFFFFFFFu, um);
        if (lane == 0) { red_u[wid] = wu; red_j[wid] = wj; red_m[wid] = wm; }
        __syncthreads();                                       // bar1
        if (wid == 0) {
            const bool v = (lane < 25);
            unsigned ru = v ? red_u[lane] : 0u;
            unsigned rj = v ? red_j[lane] : 0xFFFFFFFFu;
            unsigned rm = v ? red_m[lane] : 0xFFFFFFFFu;
            unsigned gu  = __reduce_max_sync(0xFFFFFFFFu, ru);
            unsigned gj  = __reduce_min_sync(0xFFFFFFFFu, (ru == gu) ? rj : 0xFFFFFFFFu);
            unsigned gmn = __reduce_min_sync(0xFFFFFFFFu, rm);
            if (lane == 0) {
                float smin = funmap(gmn);
                float vM1  = funmap(gu);     // sigma[M1], bit-exact
                int M1 = (int)gj;
                int jstar = M1;
                float sj  = vM1;
                if (jp >= 0) {
                    float sigjp = s_sigjp;
                    float v1 = (vM1 - smin) + 1.0f;
                    float pv = (1.0f - phiv) * ((sigjp - smin) + 1.0f);
                    if (pv > v1 || (pv == v1 && jp < M1)) { jstar = jp; sj = sigjp; }
                }
                s_smin  = smin;
                s_jstar = jstar;
                s_sj    = sj;
            }
        }
        __syncthreads();                                       // bar2
        const float smin  = s_smin;
        const int   jstar = s_jstar;
        const float sj    = s_sj;
        const int   q     = jstar % M_;      // tile-group gating index
        const int   gp    = (jp >= 0) ? (jp >> 3) : -1;

        // ---- Speculative coalesced W-column prefetch (next step) ----
        {
            const float4* wrow = (const float4*)(g_WbT + (size_t)jstar * MN_);
            cA = wrow[tid];
            cB = wrow[tid + 800];
        }
        const float wd = (tid < D_IN) ? g_WdT[(jstar >> 3) * D_IN + tid] : 0.0f;

        // Rank of q among lam (stable top-k semantics), pi-space
        float pvp = 0.0f;
        if (jp >= 0) pvp = (1.0f - phiv) * ((s_sigjp - smin) + 1.0f);
        float lamq = (lam_s[q] - smin) + 1.0f;
        if (q == gp) lamq = fmaxf(lamq, pvp);
        const int   m   = even ? mA : mB;
        const float gmv = even ? gmA : gmB;
        int flag = 0;
        if (m != q) {
            float lm = (gmv - smin) + 1.0f;
            if (m == gp) lm = fmaxf(lm, pvp);
            flag = (lm > lamq) || (lm == lamq && m < q);
        }
        const int cnt = __syncthreads_count(flag);             // bar3

        const float tt   = tanhf(sj);
        const float yval = (cnt < K_) ? tt : 0.0f;             // m_lam gate
        const float gval = (yval > 0.0f) ? yval : 0.0f;

        if (tid < D_IN)
            out[t * D_IN + tid] = (gval > 0.0f) ? fmaf(wd, gval, bdv) : bdv;

        if (yval > 0.0f) { jp = jstar; phiv = yval; }
        else             { jp = -1;    phiv = 0.0f; }
        aV = aNext;
    }

    // Final outputs: x_b (exactly one-hot 1.0), phi, psis[-1]
    if (tid == 0 && jp >= 0) {
        out[T_BATCH * D_IN + jp]           = 1.0f;   // x_b
        out[T_BATCH * D_IN + MN_ + jp]     = phiv;   // phi
        out[T_BATCH * D_IN + 2 * MN_ + jp] = phiv;   // psis[-1]
    }
}

// ---------------------------------------------------------------------------
extern "C" void kernel_launch(void* const* d_in, const int* in_sizes, int n_in,
                              void* d_out, int out_size) {
    const float* X  = (const float*)d_in[0];
    const float* Wa = (const float*)d_in[1];
    const float* ba = (const float*)d_in[2];
    const float* Wb = (const float*)d_in[3];
    const float* bb = (const float*)d_in[4];
    const float* Wd = (const float*)d_in[5];
    const float* bd = (const float*)d_in[6];
    float* out = (float*)d_out;

    prep_kernel<<<PREP_BLKS, 256>>>(X, Wa, ba, Wd, Wb);
    scan_kernel<<<1, 800>>>(bb, bd, out);
}

// round 12
// speedup vs baseline: 1.1394x; 1.0481x over previous
#include <cuda_runtime.h>
#include <cstdint>

#define T_BATCH 256
#define D_IN    784
#define M_      800
#define N_      8
#define K_      25
#define MN_     6400
#define NEG_INF (-3.402823466e38f)

// Scratch (allocation-free rule: __device__ globals)
__device__ float g_WbT[(size_t)MN_ * MN_];     // W_b transposed (163.84 MB)
__device__ float g_Abb[(size_t)T_BATCH * MN_]; // abb[t][j] = a[t][j%800] + bb[j]
__device__ float g_WdT[M_ * D_IN];             // W_d transposed

// Monotone float<->uint order mapping (no NaNs in this workload)
__device__ __forceinline__ unsigned fmap(unsigned b) {
    return (b & 0x80000000u) ? ~b : (b | 0x80000000u);
}
__device__ __forceinline__ float funmap(unsigned u) {
    unsigned b = (u & 0x80000000u) ? (u & 0x7FFFFFFFu) : ~u;
    return __uint_as_float(b);
}

// ---------------------------------------------------------------------------
// Mega prep kernel, 256 threads/block:
//   blocks [0,200)      : abb = (X @ Wa^T + ba) tiled + bb  (GEMM + epilogue)
//   blocks [200,825)    : W_d transpose (784,800) -> (800,784)
//   blocks [825,40825)  : W_b transpose 6400x6400 (DRAM-bound; overlaps GEMM)
// ---------------------------------------------------------------------------
#define GEMM_BLKS 200
#define WD_BLKS   625
#define WB_BASE   (GEMM_BLKS + WD_BLKS)
#define PREP_BLKS (WB_BASE + 200 * 200)
#define TS 36   // 144B row stride: 16B-aligned rows for float4 LDS/STS

__global__ void __launch_bounds__(256)
prep_kernel(const float* __restrict__ X, const float* __restrict__ Wa,
            const float* __restrict__ ba, const float* __restrict__ Wd,
            const float* __restrict__ Wb, const float* __restrict__ bb) {
    __shared__ __align__(16) float sh[2 * 32 * TS];
    const int b = blockIdx.x;
    const int tid = threadIdx.x;

    if (b >= WB_BASE) {
        float (*tile)[33] = (float(*)[33])sh;
        int b2 = b - WB_BASE;
        int bx = b2 % 200, by = b2 / 200;
        int tx = tid & 31, ty = tid >> 5;
        int x = bx * 32 + tx;
        int y0 = by * 32;
#pragma unroll
        for (int i = ty; i < 32; i += 8)
            tile[i][tx] = Wb[(size_t)(y0 + i) * MN_ + x];
        __syncthreads();
        int x2 = by * 32 + tx;
        int y2 = bx * 32;
#pragma unroll
        for (int i = ty; i < 32; i += 8)
            g_WbT[(size_t)(y2 + i) * MN_ + x2] = tile[tx][i];
    } else if (b < GEMM_BLKS) {
        float (*Xs)[TS] = (float(*)[TS])sh;
        float (*Ws)[TS] = (float(*)[TS])(sh + 32 * TS);
        const int bm = b % 25, bt = b / 25;
        const int lrow = tid >> 3, lc4 = tid & 7;
        const int tx = tid & 15, ty = tid >> 4;
        float c00 = 0.f, c01 = 0.f, c10 = 0.f, c11 = 0.f;
        for (int k0 = 0; k0 < D_IN; k0 += 32) {
            int kc = k0 + lc4 * 4;
            float4 xv = (kc + 3 < D_IN)
                ? *(const float4*)(X + (bt * 32 + lrow) * D_IN + kc)
                : make_float4(0.f, 0.f, 0.f, 0.f);
            float4 wv = (kc + 3 < D_IN)
                ? *(const float4*)(Wa + (bm * 32 + lrow) * D_IN + kc)
                : make_float4(0.f, 0.f, 0.f, 0.f);
            __syncthreads();
            *(float4*)&Xs[lrow][lc4 * 4] = xv;
            *(float4*)&Ws[lrow][lc4 * 4] = wv;
            __syncthreads();
#pragma unroll
            for (int k = 0; k < 32; k += 4) {
                float4 x0 = *(const float4*)&Xs[2 * ty][k];
                float4 x1 = *(const float4*)&Xs[2 * ty + 1][k];
                float4 w0 = *(const float4*)&Ws[2 * tx][k];
                float4 w1 = *(const float4*)&Ws[2 * tx + 1][k];
                c00 = fmaf(x0.x, w0.x, c00); c00 = fmaf(x0.y, w0.y, c00);
                c00 = fmaf(x0.z, w0.z, c00); c00 = fmaf(x0.w, w0.w, c00);
                c01 = fmaf(x0.x, w1.x, c01); c01 = fmaf(x0.y, w1.y, c01);
                c01 = fmaf(x0.z, w1.z, c01); c01 = fmaf(x0.w, w1.w, c01);
                c10 = fmaf(x1.x, w0.x, c10); c10 = fmaf(x1.y, w0.y, c10);
                c10 = fmaf(x1.z, w0.z, c10); c10 = fmaf(x1.w, w0.w, c10);
                c11 = fmaf(x1.x, w1.x, c11); c11 = fmaf(x1.y, w1.y, c11);
                c11 = fmaf(x1.z, w1.z, c11); c11 = fmaf(x1.w, w1.w, c11);
            }
        }
        int m0 = bm * 32 + 2 * tx, t0 = bt * 32 + 2 * ty;
        float a00 = c00 + ba[m0],     a01 = c01 + ba[m0 + 1];
        float a10 = c10 + ba[m0],     a11 = c11 + ba[m0 + 1];
        // Epilogue: abb[t][m + 800k] = a + bb[m + 800k], k = 0..7
#pragma unroll
        for (int k = 0; k < 8; ++k) {
            int j0 = m0 + 800 * k;
            float b0 = bb[j0], b1 = bb[j0 + 1];
            g_Abb[(size_t)t0 * MN_ + j0]           = a00 + b0;
            g_Abb[(size_t)t0 * MN_ + j0 + 1]       = a01 + b1;
            g_Abb[(size_t)(t0 + 1) * MN_ + j0]     = a10 + b0;
            g_Abb[(size_t)(t0 + 1) * MN_ + j0 + 1] = a11 + b1;
        }
    } else {
        float (*tile)[33] = (float(*)[33])sh;
        int r = b - GEMM_BLKS;
        int g0 = (r % 25) * 32;
        int d0 = (r / 25) * 32;
        int tx = tid & 31, ty = tid >> 5;
#pragma unroll
        for (int i = ty; i < 32; i += 8) {
            int d = d0 + i, g = g0 + tx;
            if (d < D_IN) tile[i][tx] = Wd[d * M_ + g];
        }
        __syncthreads();
#pragma unroll
        for (int i = ty; i < 32; i += 8) {
            int g = g0 + i, d = d0 + tx;
            if (d < D_IN) g_WdT[g * D_IN + d] = tile[tx][i];
        }
    }
}

// ---------------------------------------------------------------------------
// Main sequential scan: single CTA, 800 threads, instruction-minimized.
// Thread tid owns j = 4tid..4tid+3 (chunk A, half of reshape group tid>>1)
// and j = 3200+4tid.. (chunk B, half of group 400+(tid>>1)). All loads
// coalesced. jp-exclusion via one masked copy; fmax/fmin chains + one fmap
// per half-chunk; warp argmax index via ballot election; tanh scalarized.
// ---------------------------------------------------------------------------
__global__ void __launch_bounds__(800, 1)
scan_kernel(const float* __restrict__ bd, float* __restrict__ out) {
    __shared__ float lam_s[M_];                   // group max sigma excl jp
    __shared__ unsigned red_u[25], red_j[25], red_m[25];
    __shared__ float s_smin, s_tt, s_sigjp;
    __shared__ int   s_jstar;

    const int tid  = threadIdx.x;
    const int lane = tid & 31;
    const int wid  = tid >> 5;

    // Zero the x_b / phi / psi tail (d_out is poisoned)
    for (int i = tid; i < 3 * MN_; i += 800) out[T_BATCH * D_IN + i] = 0.0f;
    __syncthreads();

    const float bdv = (tid < D_IN) ? bd[tid] : 0.0f;
    const int mA  = tid >> 1;              // reshape group of chunk A
    const int mB  = 400 + (tid >> 1);      // reshape group of chunk B
    const bool even = (tid & 1) == 0;

    int   jp   = -1;     // active one-hot index of x_b / phi (-1 = zero vectors)
    float phiv = 0.0f;   // phi value at jp
    float4 cA = make_float4(0.f, 0.f, 0.f, 0.f);   // prefetched W column (0 if !use)
    float4 cB = make_float4(0.f, 0.f, 0.f, 0.f);
    float4 aA = *(const float4*)(g_Abb + 4 * tid);          // abb row 0
    float4 aB = *(const float4*)(g_Abb + 3200 + 4 * tid);

    for (int t = 0; t < T_BATCH; ++t) {
        // Prefetch next abb row at step top (full-step overlap)
        const int tn = (t + 1 < T_BATCH) ? t + 1 : 0;
        const float4 nA = *(const float4*)(g_Abb + (size_t)tn * MN_ + 4 * tid);
        const float4 nB = *(const float4*)(g_Abb + (size_t)tn * MN_ + 3200 + 4 * tid);

        // sigma = abb + W_b[:,jp] (cA/cB are exact zeros when no active one-hot)
        const float s0 = aA.x + cA.x, s1 = aA.y + cA.y;
        const float s2 = aA.z + cA.z, s3 = aA.w + cA.w;
        const float s4 = aB.x + cB.x, s5 = aB.y + cB.y;
        const float s6 = aB.z + cB.z, s7 = aB.w + cB.w;

        // jp masking (at most one element in the whole block)
        const int jdA = jp - 4 * tid;             // in [0,4) iff owner, chunk A
        const int jdB = jp - (3200 + 4 * tid);    // in [0,4) iff owner, chunk B
        const float m0 = (jdA == 0) ? NEG_INF : s0;
        const float m1 = (jdA == 1) ? NEG_INF : s1;
        const float m2 = (jdA == 2) ? NEG_INF : s2;
        const float m3 = (jdA == 3) ? NEG_INF : s3;
        const float m4 = (jdB == 0) ? NEG_INF : s4;
        const float m5 = (jdB == 1) ? NEG_INF : s5;
        const float m6 = (jdB == 2) ? NEG_INF : s6;
        const float m7 = (jdB == 3) ? NEG_INF : s7;
        if (jdA >= 0 && jdA < 4)
            s_sigjp = (jdA & 2) ? ((jdA & 1) ? s3 : s2) : ((jdA & 1) ? s1 : s0);
        else if (jdB >= 0 && jdB < 4)
            s_sigjp = (jdB & 2) ? ((jdB & 1) ? s7 : s6) : ((jdB & 1) ? s5 : s4);

        // Chains: masked half-group maxes, raw global min
        float gmAh = fmaxf(fmaxf(m0, m1), fmaxf(m2, m3));
        float gmBh = fmaxf(fmaxf(m4, m5), fmaxf(m6, m7));
        float vmin = fminf(fminf(fminf(s0, s1), fminf(s2, s3)),
                           fminf(fminf(s4, s5), fminf(s6, s7)));

        // Pair-combine -> full masked group maxes (lam), store
        const float gmA = fmaxf(gmAh, __shfl_xor_sync(0xFFFFFFFFu, gmAh, 1));
        const float gmB = fmaxf(gmBh, __shfl_xor_sync(0xFFFFFFFFu, gmBh, 1));
        if (even) lam_s[mA] = gmA;
        else      lam_s[mB] = gmB;

        // Warp reductions: max value + min; index via ballot election
        const unsigned uA = fmap(__float_as_uint(gmAh));
        const unsigned uB = fmap(__float_as_uint(gmBh));
        const unsigned wu = __reduce_max_sync(0xFFFFFFFFu, max(uA, uB));
        const unsigned wm = __reduce_min_sync(0xFFFFFFFFu, fmap(__float_as_uint(vmin)));
        const unsigned ballA = __ballot_sync(0xFFFFFFFFu, uA == wu);
        const unsigned ballB = __ballot_sync(0xFFFFFFFFu, uB == wu);
        const bool selA = (ballA != 0);
        const int  src  = __ffs(selA ? ballA : ballB) - 1;
        if (lane == src) {
            // Elected lane resolves its local first index (chunk A priority
            // preserves global first-index tie semantics: all A j's < B j's)
            int idx, base;
            if (selA) {
                const float v = gmAh;
                idx = (m0 == v) ? 0 : (m1 == v) ? 1 : (m2 == v) ? 2 : 3;
                base = 4 * tid;
            } else {
                const float v = gmBh;
                idx = (m4 == v) ? 0 : (m5 == v) ? 1 : (m6 == v) ? 2 : 3;
                base = 3200 + 4 * tid;
            }
            red_j[wid] = (unsigned)(base + idx);
        }
        if (lane == 0) { red_u[wid] = wu; red_m[wid] = wm; }
        __syncthreads();                                       // bar1
        if (wid == 0) {
            const bool v = (lane < 25);
            unsigned ru = v ? red_u[lane] : 0u;
            unsigned rj = v ? red_j[lane] : 0xFFFFFFFFu;
            unsigned rm = v ? red_m[lane] : 0xFFFFFFFFu;
            unsigned gu  = __reduce_max_sync(0xFFFFFFFFu, ru);
            unsigned gj  = __reduce_min_sync(0xFFFFFFFFu, (ru == gu) ? rj : 0xFFFFFFFFu);
            unsigned gmn = __reduce_min_sync(0xFFFFFFFFu, rm);
            if (lane == 0) {
                float smin = funmap(gmn);
                float vM1  = funmap(gu);     // sigma[M1], bit-exact
                int M1 = (int)gj;
                int jstar = M1;
                float sj  = vM1;
                if (jp >= 0) {
                    float sigjp = s_sigjp;
                    float v1 = (vM1 - smin) + 1.0f;
                    float pv = (1.0f - phiv) * ((sigjp - smin) + 1.0f);
                    if (pv > v1 || (pv == v1 && jp < M1)) { jstar = jp; sj = sigjp; }
                }
                s_smin  = smin;
                s_jstar = jstar;
                s_tt    = tanhf(sj);     // scalarized: saves ~20 instr x 800 thr
            }
        }
        __syncthreads();                                       // bar2
        const float smin  = s_smin;
        const int   jstar = s_jstar;
        const int   q     = jstar % M_;      // tile-group gating index
        const int   gp    = (jp >= 0) ? (jp >> 3) : -1;

        // Speculative coalesced W-column prefetch (next step)
        {
            const float4* wrow = (const float4*)(g_WbT + (size_t)jstar * MN_);
            cA = wrow[tid];
            cB = wrow[tid + 800];
        }
        const float wd = (tid < D_IN) ? g_WdT[(jstar >> 3) * D_IN + tid] : 0.0f;

        // Rank of q among lam (stable top-k semantics), pi-space
        float pvp = 0.0f;
        if (jp >= 0) pvp = (1.0f - phiv) * ((s_sigjp - smin) + 1.0f);
        float lamq = (lam_s[q] - smin) + 1.0f;
        if (q == gp) lamq = fmaxf(lamq, pvp);
        const int   m   = even ? mA : mB;
        const float gmv = even ? gmA : gmB;
        int flag = 0;
        if (m != q) {
            float lm = (gmv - smin) + 1.0f;
            if (m == gp) lm = fmaxf(lm, pvp);
            flag = (lm > lamq) || (lm == lamq && m < q);
        }
        const int cnt = __syncthreads_count(flag);             // bar3

        const float tt   = s_tt;
        const float yval = (cnt < K_) ? tt : 0.0f;             // m_lam gate
        const float gval = (yval > 0.0f) ? yval : 0.0f;

        if (tid < D_IN)
            out[t * D_IN + tid] = (gval > 0.0f) ? fmaf(wd, gval, bdv) : bdv;

        if (yval > 0.0f) {
            jp = jstar; phiv = yval;
        } else {
            jp = -1; phiv = 0.0f;
            cA = make_float4(0.f, 0.f, 0.f, 0.f);   // sigma add is unconditional
            cB = make_float4(0.f, 0.f, 0.f, 0.f);
        }
        aA = nA; aB = nB;
    }

    // Final outputs: x_b (exactly one-hot 1.0), phi, psis[-1]
    if (tid == 0 && jp >= 0) {
        out[T_BATCH * D_IN + jp]           = 1.0f;   // x_b
        out[T_BATCH * D_IN + MN_ + jp]     = phiv;   // phi
        out[T_BATCH * D_IN + 2 * MN_ + jp] = phiv;   // psis[-1]
    }
}

// ---------------------------------------------------------------------------
extern "C" void kernel_launch(void* const* d_in, const int* in_sizes, int n_in,
                              void* d_out, int out_size) {
    const float* X  = (const float*)d_in[0];
    const float* Wa = (const float*)d_in[1];
    const float* ba = (const float*)d_in[2];
    const float* Wb = (const float*)d_in[3];
    const float* bb = (const float*)d_in[4];
    const float* Wd = (const float*)d_in[5];
    const float* bd = (const float*)d_in[6];
    float* out = (float*)d_out;

    prep_kernel<<<PREP_BLKS, 256>>>(X, Wa, ba, Wd, Wb, bb);
    scan_kernel<<<1, 800>>>(bd, out);
}

// round 13
// speedup vs baseline: 1.1456x; 1.0055x over previous
#include <cuda_runtime.h>
#include <cstdint>

#define T_BATCH 256
#define D_IN    784
#define M_      800
#define N_      8
#define K_      25
#define MN_     6400
#define NEG_INF (-3.402823466e38f)

// Scratch (allocation-free rule: __device__ globals)
__device__ float g_WbT[(size_t)MN_ * MN_];     // W_b transposed (163.84 MB)
__device__ float g_Abb[(size_t)T_BATCH * MN_]; // abb[t][j] = a[t][j%800] + bb[j]
__device__ float g_WdT[M_ * D_IN];             // W_d transposed

// Monotone float<->uint order mapping (no NaNs in this workload)
__device__ __forceinline__ unsigned fmap(unsigned b) {
    return (b & 0x80000000u) ? ~b : (b | 0x80000000u);
}
__device__ __forceinline__ float funmap(unsigned u) {
    unsigned b = (u & 0x80000000u) ? (u & 0x7FFFFFFFu) : ~u;
    return __uint_as_float(b);
}

// ---------------------------------------------------------------------------
// Mega prep kernel (unchanged; ~64us, near the 328MB DRAM floor)
// ---------------------------------------------------------------------------
#define GEMM_BLKS 200
#define WD_BLKS   625
#define WB_BASE   (GEMM_BLKS + WD_BLKS)
#define PREP_BLKS (WB_BASE + 200 * 200)
#define TS 36   // 144B row stride: 16B-aligned rows for float4 LDS/STS

__global__ void __launch_bounds__(256)
prep_kernel(const float* __restrict__ X, const float* __restrict__ Wa,
            const float* __restrict__ ba, const float* __restrict__ Wd,
            const float* __restrict__ Wb, const float* __restrict__ bb) {
    __shared__ __align__(16) float sh[2 * 32 * TS];
    const int b = blockIdx.x;
    const int tid = threadIdx.x;

    if (b >= WB_BASE) {
        float (*tile)[33] = (float(*)[33])sh;
        int b2 = b - WB_BASE;
        int bx = b2 % 200, by = b2 / 200;
        int tx = tid & 31, ty = tid >> 5;
        int x = bx * 32 + tx;
        int y0 = by * 32;
#pragma unroll
        for (int i = ty; i < 32; i += 8)
            tile[i][tx] = Wb[(size_t)(y0 + i) * MN_ + x];
        __syncthreads();
        int x2 = by * 32 + tx;
        int y2 = bx * 32;
#pragma unroll
        for (int i = ty; i < 32; i += 8)
            g_WbT[(size_t)(y2 + i) * MN_ + x2] = tile[tx][i];
    } else if (b < GEMM_BLKS) {
        float (*Xs)[TS] = (float(*)[TS])sh;
        float (*Ws)[TS] = (float(*)[TS])(sh + 32 * TS);
        const int bm = b % 25, bt = b / 25;
        const int lrow = tid >> 3, lc4 = tid & 7;
        const int tx = tid & 15, ty = tid >> 4;
        float c00 = 0.f, c01 = 0.f, c10 = 0.f, c11 = 0.f;
        for (int k0 = 0; k0 < D_IN; k0 += 32) {
            int kc = k0 + lc4 * 4;
            float4 xv = (kc + 3 < D_IN)
                ? *(const float4*)(X + (bt * 32 + lrow) * D_IN + kc)
                : make_float4(0.f, 0.f, 0.f, 0.f);
            float4 wv = (kc + 3 < D_IN)
                ? *(const float4*)(Wa + (bm * 32 + lrow) * D_IN + kc)
                : make_float4(0.f, 0.f, 0.f, 0.f);
            __syncthreads();
            *(float4*)&Xs[lrow][lc4 * 4] = xv;
            *(float4*)&Ws[lrow][lc4 * 4] = wv;
            __syncthreads();
#pragma unroll
            for (int k = 0; k < 32; k += 4) {
                float4 x0 = *(const float4*)&Xs[2 * ty][k];
                float4 x1 = *(const float4*)&Xs[2 * ty + 1][k];
                float4 w0 = *(const float4*)&Ws[2 * tx][k];
                float4 w1 = *(const float4*)&Ws[2 * tx + 1][k];
                c00 = fmaf(x0.x, w0.x, c00); c00 = fmaf(x0.y, w0.y, c00);
                c00 = fmaf(x0.z, w0.z, c00); c00 = fmaf(x0.w, w0.w, c00);
                c01 = fmaf(x0.x, w1.x, c01); c01 = fmaf(x0.y, w1.y, c01);
                c01 = fmaf(x0.z, w1.z, c01); c01 = fmaf(x0.w, w1.w, c01);
                c10 = fmaf(x1.x, w0.x, c10); c10 = fmaf(x1.y, w0.y, c10);
                c10 = fmaf(x1.z, w0.z, c10); c10 = fmaf(x1.w, w0.w, c10);
                c11 = fmaf(x1.x, w1.x, c11); c11 = fmaf(x1.y, w1.y, c11);
                c11 = fmaf(x1.z, w1.z, c11); c11 = fmaf(x1.w, w1.w, c11);
            }
        }
        int m0 = bm * 32 + 2 * tx, t0 = bt * 32 + 2 * ty;
        float a00 = c00 + ba[m0],     a01 = c01 + ba[m0 + 1];
        float a10 = c10 + ba[m0],     a11 = c11 + ba[m0 + 1];
#pragma unroll
        for (int k = 0; k < 8; ++k) {
            int j0 = m0 + 800 * k;
            float b0 = bb[j0], b1 = bb[j0 + 1];
            g_Abb[(size_t)t0 * MN_ + j0]           = a00 + b0;
            g_Abb[(size_t)t0 * MN_ + j0 + 1]       = a01 + b1;
            g_Abb[(size_t)(t0 + 1) * MN_ + j0]     = a10 + b0;
            g_Abb[(size_t)(t0 + 1) * MN_ + j0 + 1] = a11 + b1;
        }
    } else {
        float (*tile)[33] = (float(*)[33])sh;
        int r = b - GEMM_BLKS;
        int g0 = (r % 25) * 32;
        int d0 = (r / 25) * 32;
        int tx = tid & 31, ty = tid >> 5;
#pragma unroll
        for (int i = ty; i < 32; i += 8) {
            int d = d0 + i, g = g0 + tx;
            if (d < D_IN) tile[i][tx] = Wd[d * M_ + g];
        }
        __syncthreads();
#pragma unroll
        for (int i = ty; i < 32; i += 8) {
            int g = g0 + i, d = d0 + tx;
            if (d < D_IN) g_WdT[g * D_IN + d] = tile[tx][i];
        }
    }
}

// ---------------------------------------------------------------------------
// Main sequential scan: single CTA, 800 threads, 2 barriers/step.
// After bar1 every warp redundantly finishes the 25-wide reduction (identical
// deterministic result) -> no warp0 serialization, no bar2. W-column + wd
// prefetches issue immediately after bar1; output STG deferred one step.
// ---------------------------------------------------------------------------
__global__ void __launch_bounds__(800, 1)
scan_kernel(const float* __restrict__ bd, float* __restrict__ out) {
    __shared__ float lam_s[M_];                   // group max sigma excl jp
    __shared__ unsigned red_u[32], red_j[32], red_m[32];
    __shared__ float s_sigjp;

    const int tid  = threadIdx.x;
    const int lane = tid & 31;
    const int wid  = tid >> 5;

    // Zero the x_b / phi / psi tail (d_out is poisoned)
    for (int i = tid; i < 3 * MN_; i += 800) out[T_BATCH * D_IN + i] = 0.0f;
    __syncthreads();

    const float bdv = (tid < D_IN) ? bd[tid] : 0.0f;
    const int mA  = tid >> 1;              // reshape group of chunk A
    const int mB  = 400 + (tid >> 1);      // reshape group of chunk B
    const bool even = (tid & 1) == 0;

    int   jp   = -1;     // active one-hot index of x_b / phi (-1 = zero vectors)
    float phiv = 0.0f;   // phi value at jp
    float wdP = 0.0f, gvalP = 0.0f;                 // deferred output of step t-1
    float4 cA = make_float4(0.f, 0.f, 0.f, 0.f);    // prefetched W column (0 if !use)
    float4 cB = make_float4(0.f, 0.f, 0.f, 0.f);
    float4 aA = *(const float4*)(g_Abb + 4 * tid);  // abb row 0
    float4 aB = *(const float4*)(g_Abb + 3200 + 4 * tid);

    for (int t = 0; t < T_BATCH; ++t) {
        // Prefetch next abb row (consumed next step -> full overlap)
        const int tn = (t + 1 < T_BATCH) ? t + 1 : 0;
        const float4 nA = *(const float4*)(g_Abb + (size_t)tn * MN_ + 4 * tid);
        const float4 nB = *(const float4*)(g_Abb + (size_t)tn * MN_ + 3200 + 4 * tid);

        // Deferred output store for step t-1 (wd data long since arrived)
        if (t > 0 && tid < D_IN)
            out[(t - 1) * D_IN + tid] =
                (gvalP > 0.0f) ? fmaf(wdP, gvalP, bdv) : bdv;

        // sigma = abb + W_b[:,jp] (cA/cB exact zeros when no active one-hot)
        const float s0 = aA.x + cA.x, s1 = aA.y + cA.y;
        const float s2 = aA.z + cA.z, s3 = aA.w + cA.w;
        const float s4 = aB.x + cB.x, s5 = aB.y + cB.y;
        const float s6 = aB.z + cB.z, s7 = aB.w + cB.w;

        // jp masking (at most one element in the whole block)
        const int jdA = jp - 4 * tid;
        const int jdB = jp - (3200 + 4 * tid);
        const float m0 = (jdA == 0) ? NEG_INF : s0;
        const float m1 = (jdA == 1) ? NEG_INF : s1;
        const float m2 = (jdA == 2) ? NEG_INF : s2;
        const float m3 = (jdA == 3) ? NEG_INF : s3;
        const float m4 = (jdB == 0) ? NEG_INF : s4;
        const float m5 = (jdB == 1) ? NEG_INF : s5;
        const float m6 = (jdB == 2) ? NEG_INF : s6;
        const float m7 = (jdB == 3) ? NEG_INF : s7;
        if (jdA >= 0 && jdA < 4)
            s_sigjp = (jdA & 2) ? ((jdA & 1) ? s3 : s2) : ((jdA & 1) ? s1 : s0);
        else if (jdB >= 0 && jdB < 4)
            s_sigjp = (jdB & 2) ? ((jdB & 1) ? s7 : s6) : ((jdB & 1) ? s5 : s4);

        // Chains: masked half-group maxes, raw global min
        const float gmAh = fmaxf(fmaxf(m0, m1), fmaxf(m2, m3));
        const float gmBh = fmaxf(fmaxf(m4, m5), fmaxf(m6, m7));
        const float vmin = fminf(fminf(fminf(s0, s1), fminf(s2, s3)),
                                 fminf(fminf(s4, s5), fminf(s6, s7)));

        // Pair-combine -> full masked group maxes (lam), store
        const float gmA = fmaxf(gmAh, __shfl_xor_sync(0xFFFFFFFFu, gmAh, 1));
        const float gmB = fmaxf(gmBh, __shfl_xor_sync(0xFFFFFFFFu, gmBh, 1));
        if (even) lam_s[mA] = gmA;
        else      lam_s[mB] = gmB;

        // Warp reductions: max value + min; argmax index via ballot election
        const unsigned uA = fmap(__float_as_uint(gmAh));
        const unsigned uB = fmap(__float_as_uint(gmBh));
        const unsigned wu = __reduce_max_sync(0xFFFFFFFFu, max(uA, uB));
        const unsigned wm = __reduce_min_sync(0xFFFFFFFFu, fmap(__float_as_uint(vmin)));
        const unsigned ballA = __ballot_sync(0xFFFFFFFFu, uA == wu);
        const unsigned ballB = __ballot_sync(0xFFFFFFFFu, uB == wu);
        const bool selA = (ballA != 0);
        const int  src  = __ffs(selA ? ballA : ballB) - 1;
        if (lane == src) {
            // Chunk-A priority preserves global first-index tie semantics
            int idx, base;
            if (selA) {
                const float v = gmAh;
                idx = (m0 == v) ? 0 : (m1 == v) ? 1 : (m2 == v) ? 2 : 3;
                base = 4 * tid;
            } else {
                const float v = gmBh;
                idx = (m4 == v) ? 0 : (m5 == v) ? 1 : (m6 == v) ? 2 : 3;
                base = 3200 + 4 * tid;
            }
            red_j[wid] = (unsigned)(base + idx);
        }
        if (lane == 0) { red_u[wid] = wu; red_m[wid] = wm; }
        __syncthreads();                                       // bar1

        // ---- Redundant final resolve, identical in every warp ----
        const bool v25 = (lane < 25);
        const unsigned ru = v25 ? red_u[lane] : 0u;
        const unsigned rj = v25 ? red_j[lane] : 0xFFFFFFFFu;
        const unsigned rm = v25 ? red_m[lane] : 0xFFFFFFFFu;
        const unsigned gu  = __reduce_max_sync(0xFFFFFFFFu, ru);
        const unsigned gj  = __reduce_min_sync(0xFFFFFFFFu, (ru == gu) ? rj : 0xFFFFFFFFu);
        const unsigned gmn = __reduce_min_sync(0xFFFFFFFFu, rm);
        const float smin = funmap(gmn);
        const float vM1  = funmap(gu);       // sigma[M1], bit-exact
        const int   M1   = (int)gj;
        int   jstar = M1;
        float sj    = vM1;
        float sigjp = 0.0f;
        if (jp >= 0) {
            sigjp = s_sigjp;                 // LDS broadcast
            const float v1 = (vM1 - smin) + 1.0f;
            const float pv = (1.0f - phiv) * ((sigjp - smin) + 1.0f);
            if (pv > v1 || (pv == v1 && jp < M1)) { jstar = jp; sj = sigjp; }
        }

        // ---- Prefetches issue here: rank + count + output between issue/use
        {
            const float4* wrow = (const float4*)(g_WbT + (size_t)jstar * MN_);
            cA = wrow[tid];              // safe: this step's sigma already built
            cB = wrow[tid + 800];
        }
        const float wd = (tid < D_IN) ? g_WdT[(jstar >> 3) * D_IN + tid] : 0.0f;

        // Rank of q among lam (stable top-k semantics), pi-space
        const int q  = jstar % M_;
        const int gp = (jp >= 0) ? (jp >> 3) : -1;
        float pvp = 0.0f;
        if (jp >= 0) pvp = (1.0f - phiv) * ((sigjp - smin) + 1.0f);
        float lamq = (lam_s[q] - smin) + 1.0f;
        if (q == gp) lamq = fmaxf(lamq, pvp);
        const int   m   = even ? mA : mB;
        const float gmv = even ? gmA : gmB;
        int flag = 0;
        if (m != q) {
            float lm = (gmv - smin) + 1.0f;
            if (m == gp) lm = fmaxf(lm, pvp);
            flag = (lm > lamq) || (lm == lamq && m < q);
        }
        const int cnt = __syncthreads_count(flag);             // bar2

        // Winner iff rank < K and tanh positive (tanh>0 <=> sj>0)
        const bool win = (cnt < K_) && (sj > 0.0f);
        float yv = 0.0f;
        if (win) yv = tanhf(sj);             // uniform branch, skipped on losses

        wdP = wd; gvalP = yv;                // deferred store next step
        if (win) {
            jp = jstar; phiv = yv;
        } else {
            jp = -1; phiv = 0.0f;
            cA = make_float4(0.f, 0.f, 0.f, 0.f);
            cB = make_float4(0.f, 0.f, 0.f, 0.f);
        }
        aA = nA; aB = nB;
    }

    // Final deferred store (t = T_BATCH-1)
    if (tid < D_IN)
        out[(T_BATCH - 1) * D_IN + tid] =
            (gvalP > 0.0f) ? fmaf(wdP, gvalP, bdv) : bdv;

    // Final outputs: x_b (exactly one-hot 1.0), phi, psis[-1]
    if (tid == 0 && jp >= 0) {
        out[T_BATCH * D_IN + jp]           = 1.0f;   // x_b
        out[T_BATCH * D_IN + MN_ + jp]     = phiv;   // phi
        out[T_BATCH * D_IN + 2 * MN_ + jp] = phiv;   // psis[-1]
    }
}

// ---------------------------------------------------------------------------
extern "C" void kernel_launch(void* const* d_in, const int* in_sizes, int n_in,
                              void* d_out, int out_size) {
    const float* X  = (const float*)d_in[0];
    const float* Wa = (const float*)d_in[1];
    const float* ba = (const float*)d_in[2];
    const float* Wb = (const float*)d_in[3];
    const float* bb = (const float*)d_in[4];
    const float* Wd = (const float*)d_in[5];
    const float* bd = (const float*)d_in[6];
    float* out = (float*)d_out;

    prep_kernel<<<PREP_BLKS, 256>>>(X, Wa, ba, Wd, Wb, bb);
    scan_kernel<<<1, 800>>>(bd, out);
}

// round 14
// speedup vs baseline: 1.1882x; 1.0372x over previous
#include <cuda_runtime.h>
#include <cstdint>

#define T_BATCH 256
#define D_IN    784
#define M_      800
#define N_      8
#define K_      25
#define MN_     6400
#define NEG_INF (-3.402823466e38f)
#define POS_INF (3.402823466e38f)

// Scratch (allocation-free rule: __device__ globals)
__device__ float g_WbT[(size_t)MN_ * MN_];     // W_b^T, rows sigma-permuted (164 MB)
__device__ float g_Abb[(size_t)T_BATCH * MN_]; // abb[t][sig(j)] = a[t][j%800]+bb[j]
__device__ float g_WdT[M_ * D_IN];             // W_d transposed

// Within-row permutation: j = 16q + 4k + i  ->  pos = 1600k + 4q + i.
// Thread q then owns 16 consecutive j via 4 coalesced float4 loads at
// positions {q, 400+q, 800+q, 1200+q}.
__device__ __forceinline__ int sig(int j) {
    return ((j >> 2) & 3) * 1600 + ((j >> 4) << 2) + (j & 3);
}

// Monotone float<->uint order mapping (no NaNs in this workload)
__device__ __forceinline__ unsigned fmap(unsigned b) {
    return (b & 0x80000000u) ? ~b : (b | 0x80000000u);
}
__device__ __forceinline__ float funmap(unsigned u) {
    unsigned b = (u & 0x80000000u) ? (u & 0x7FFFFFFFu) : ~u;
    return __uint_as_float(b);
}

// ---------------------------------------------------------------------------
// Mega prep kernel (layout-permuted stores; same DRAM byte totals)
// ---------------------------------------------------------------------------
#define GEMM_BLKS 200
#define WD_BLKS   625
#define WB_BASE   (GEMM_BLKS + WD_BLKS)
#define PREP_BLKS (WB_BASE + 200 * 200)
#define TS 36   // 144B row stride: 16B-aligned rows for float4 LDS/STS

__global__ void __launch_bounds__(256)
prep_kernel(const float* __restrict__ X, const float* __restrict__ Wa,
            const float* __restrict__ ba, const float* __restrict__ Wd,
            const float* __restrict__ Wb, const float* __restrict__ bb) {
    __shared__ __align__(16) float sh[2 * 32 * TS];
    const int b = blockIdx.x;
    const int tid = threadIdx.x;

    if (b >= WB_BASE) {
        // W_b transpose with sigma-permuted in-row (j) index
        float (*tile)[33] = (float(*)[33])sh;
        int b2 = b - WB_BASE;
        int bx = b2 % 200, by = b2 / 200;
        int tx = tid & 31, ty = tid >> 5;
        int x = bx * 32 + tx;
        int y0 = by * 32;
#pragma unroll
        for (int i = ty; i < 32; i += 8)
            tile[i][tx] = Wb[(size_t)(y0 + i) * MN_ + x];
        __syncthreads();
        int x2 = by * 32 + tx;       // in-row (j) index before permutation
        int y2 = bx * 32;            // row (W column) index
        int px = sig(x2);
#pragma unroll
        for (int i = ty; i < 32; i += 8)
            g_WbT[(size_t)(y2 + i) * MN_ + px] = tile[tx][i];
    } else if (b < GEMM_BLKS) {
        float (*Xs)[TS] = (float(*)[TS])sh;
        float (*Ws)[TS] = (float(*)[TS])(sh + 32 * TS);
        const int bm = b % 25, bt = b / 25;
        const int lrow = tid >> 3, lc4 = tid & 7;
        const int tx = tid & 15, ty = tid >> 4;
        float c00 = 0.f, c01 = 0.f, c10 = 0.f, c11 = 0.f;
        for (int k0 = 0; k0 < D_IN; k0 += 32) {
            int kc = k0 + lc4 * 4;
            float4 xv = (kc + 3 < D_IN)
                ? *(const float4*)(X + (bt * 32 + lrow) * D_IN + kc)
                : make_float4(0.f, 0.f, 0.f, 0.f);
            float4 wv = (kc + 3 < D_IN)
                ? *(const float4*)(Wa + (bm * 32 + lrow) * D_IN + kc)
                : make_float4(0.f, 0.f, 0.f, 0.f);
            __syncthreads();
            *(float4*)&Xs[lrow][lc4 * 4] = xv;
            *(float4*)&Ws[lrow][lc4 * 4] = wv;
            __syncthreads();
#pragma unroll
            for (int k = 0; k < 32; k += 4) {
                float4 x0 = *(const float4*)&Xs[2 * ty][k];
                float4 x1 = *(const float4*)&Xs[2 * ty + 1][k];
                float4 w0 = *(const float4*)&Ws[2 * tx][k];
                float4 w1 = *(const float4*)&Ws[2 * tx + 1][k];
                c00 = fmaf(x0.x, w0.x, c00); c00 = fmaf(x0.y, w0.y, c00);
                c00 = fmaf(x0.z, w0.z, c00); c00 = fmaf(x0.w, w0.w, c00);
                c01 = fmaf(x0.x, w1.x, c01); c01 = fmaf(x0.y, w1.y, c01);
                c01 = fmaf(x0.z, w1.z, c01); c01 = fmaf(x0.w, w1.w, c01);
                c10 = fmaf(x1.x, w0.x, c10); c10 = fmaf(x1.y, w0.y, c10);
                c10 = fmaf(x1.z, w0.z, c10); c10 = fmaf(x1.w, w0.w, c10);
                c11 = fmaf(x1.x, w1.x, c11); c11 = fmaf(x1.y, w1.y, c11);
                c11 = fmaf(x1.z, w1.z, c11); c11 = fmaf(x1.w, w1.w, c11);
            }
        }
        int m0 = bm * 32 + 2 * tx, t0 = bt * 32 + 2 * ty;   // m0 even
        float a00 = c00 + ba[m0],     a01 = c01 + ba[m0 + 1];
        float a10 = c10 + ba[m0],     a11 = c11 + ba[m0 + 1];
#pragma unroll
        for (int k = 0; k < 8; ++k) {
            int j0 = m0 + 800 * k;
            int p0 = sig(j0);            // sig(j0+1) == p0+1 (j0 even)
            float b0 = bb[j0], b1 = bb[j0 + 1];
            g_Abb[(size_t)t0 * MN_ + p0]           = a00 + b0;
            g_Abb[(size_t)t0 * MN_ + p0 + 1]       = a01 + b1;
            g_Abb[(size_t)(t0 + 1) * MN_ + p0]     = a10 + b0;
            g_Abb[(size_t)(t0 + 1) * MN_ + p0 + 1] = a11 + b1;
        }
    } else {
        float (*tile)[33] = (float(*)[33])sh;
        int r = b - GEMM_BLKS;
        int g0 = (r % 25) * 32;
        int d0 = (r / 25) * 32;
        int tx = tid & 31, ty = tid >> 5;
#pragma unroll
        for (int i = ty; i < 32; i += 8) {
            int d = d0 + i, g = g0 + tx;
            if (d < D_IN) tile[i][tx] = Wd[d * M_ + g];
        }
        __syncthreads();
#pragma unroll
        for (int i = ty; i < 32; i += 8) {
            int g = g0 + i, d = d0 + tx;
            if (d < D_IN) g_WdT[g * D_IN + d] = tile[tx][i];
        }
    }
}

// ---------------------------------------------------------------------------
// Main sequential scan: single CTA, 416 threads (13 warps; tids 400-415 are
// dummies). Active thread tid owns j = 16tid..16tid+15 (reshape groups 2tid,
// 2tid+1, both complete) via 4 coalesced float4 loads from the permuted
// arrays. 2 barriers/step; redundant post-bar1 resolve in every warp.
// ---------------------------------------------------------------------------
__global__ void __launch_bounds__(416, 1)
scan_kernel(const float* __restrict__ bd, float* __restrict__ out) {
    __shared__ float lam_s[M_];
    __shared__ unsigned red_u[16], red_j[16], red_m[16];
    __shared__ int red_c[16];
    __shared__ float s_sigjp, s_tt;

    const int tid  = threadIdx.x;
    const int lane = tid & 31;
    const int wid  = tid >> 5;
    const bool act = tid < 400;
    const int  ft  = act ? tid : 0;          // safe load index for dummies

    // Zero the x_b / phi / psi tail (d_out is poisoned)
    for (int i = tid; i < 3 * MN_; i += 416) out[T_BATCH * D_IN + i] = 0.0f;
    __syncthreads();

    const float bdv0 = bd[tid];                                       // tid<784
    const float bdv1 = (tid < D_IN - 416) ? bd[tid + 416] : 0.0f;     // tid<368

    int   jp   = -1;
    float phiv = 0.0f;
    float wdP0 = 0.f, wdP1 = 0.f, gvalP = 0.f;
    float4 c0 = make_float4(0,0,0,0), c1 = make_float4(0,0,0,0);
    float4 c2 = make_float4(0,0,0,0), c3 = make_float4(0,0,0,0);
    const float4* ab0 = (const float4*)g_Abb;
    float4 a0 = ab0[ft], a1 = ab0[400+ft], a2 = ab0[800+ft], a3 = ab0[1200+ft];

    for (int t = 0; t < T_BATCH; ++t) {
        // Prefetch next abb row (consumed next step)
        const int tn = (t + 1 < T_BATCH) ? t + 1 : 0;
        const float4* ar = (const float4*)g_Abb + (unsigned)tn * 1600u;
        const float4 n0 = ar[ft], n1 = ar[400+ft], n2 = ar[800+ft], n3 = ar[1200+ft];

        // Deferred output store for step t-1
        if (t > 0) {
            out[(t-1) * D_IN + tid] =
                (gvalP > 0.f) ? fmaf(wdP0, gvalP, bdv0) : bdv0;
            if (tid < D_IN - 416)
                out[(t-1) * D_IN + tid + 416] =
                    (gvalP > 0.f) ? fmaf(wdP1, gvalP, bdv1) : bdv1;
        }

        // sigma (c* are exact zeros when no active one-hot); s[e] <-> j=16tid+e
        float s[16];
        s[0]=a0.x+c0.x;  s[1]=a0.y+c0.y;  s[2]=a0.z+c0.z;  s[3]=a0.w+c0.w;
        s[4]=a1.x+c1.x;  s[5]=a1.y+c1.y;  s[6]=a1.z+c1.z;  s[7]=a1.w+c1.w;
        s[8]=a2.x+c2.x;  s[9]=a2.y+c2.y;  s[10]=a2.z+c2.z; s[11]=a2.w+c2.w;
        s[12]=a3.x+c3.x; s[13]=a3.y+c3.y; s[14]=a3.z+c3.z; s[15]=a3.w+c3.w;

        // jp masking + publication: only the owner warp pays (uniform branch)
        float msk[16];
#pragma unroll
        for (int e = 0; e < 16; ++e) msk[e] = s[e];
        if (jp >= 0 && wid == (jp >> 9)) {
            const int jd = jp - 16 * tid;
            if (jd >= 0 && jd < 16) {
                float v = s[0];
#pragma unroll
                for (int e = 1; e < 16; ++e) v = (jd == e) ? s[e] : v;
                s_sigjp = v;
#pragma unroll
                for (int e = 0; e < 16; ++e) if (jd == e) msk[e] = NEG_INF;
            }
        }

        // Masked group maxes (lam) + raw global min
        float gmA = fmaxf(fmaxf(fmaxf(msk[0],msk[1]),fmaxf(msk[2],msk[3])),
                          fmaxf(fmaxf(msk[4],msk[5]),fmaxf(msk[6],msk[7])));
        float gmB = fmaxf(fmaxf(fmaxf(msk[8],msk[9]),fmaxf(msk[10],msk[11])),
                          fmaxf(fmaxf(msk[12],msk[13]),fmaxf(msk[14],msk[15])));
        float vmin = fminf(
            fminf(fminf(fminf(s[0],s[1]),fminf(s[2],s[3])),
                  fminf(fminf(s[4],s[5]),fminf(s[6],s[7]))),
            fminf(fminf(fminf(s[8],s[9]),fminf(s[10],s[11])),
                  fminf(fminf(s[12],s[13]),fminf(s[14],s[15]))));
        if (!act) { gmA = NEG_INF; gmB = NEG_INF; vmin = POS_INF; }
        if (act) { lam_s[2*tid] = gmA; lam_s[2*tid+1] = gmB; }

        // Warp reduction: max value (argmax) + min; single-ballot election
        const float tmax = fmaxf(gmA, gmB);
        const unsigned wu = __reduce_max_sync(0xFFFFFFFFu, fmap(__float_as_uint(tmax)));
        const unsigned wm = __reduce_min_sync(0xFFFFFFFFu, fmap(__float_as_uint(vmin)));
        const float wv = funmap(wu);
        const unsigned ball = __ballot_sync(0xFFFFFFFFu, tmax == wv);
        if (lane == __ffs(ball) - 1) {
            // Lowest lane = lowest j base; local first index = global tie rule
            int idx = 15;
#pragma unroll
            for (int e = 14; e >= 0; --e) idx = (msk[e] == wv) ? e : idx;
            red_j[wid] = (unsigned)(16 * tid + idx);
        }
        if (lane == 0) { red_u[wid] = wu; red_m[wid] = wm; }
        __syncthreads();                                       // bar1

        // Redundant final resolve, identical in every warp
        const bool v13 = (lane < 13);
        const unsigned ru = v13 ? red_u[lane] : 0u;
        const unsigned rj = v13 ? red_j[lane] : 0xFFFFFFFFu;
        const unsigned rm = v13 ? red_m[lane] : 0xFFFFFFFFu;
        const unsigned gu  = __reduce_max_sync(0xFFFFFFFFu, ru);
        const unsigned gj  = __reduce_min_sync(0xFFFFFFFFu, (ru == gu) ? rj : 0xFFFFFFFFu);
        const unsigned gmn = __reduce_min_sync(0xFFFFFFFFu, rm);
        const float smin = funmap(gmn);
        const float vM1  = funmap(gu);       // sigma[M1], bit-exact
        const int   M1   = (int)gj;
        int   jstar = M1;
        float sj    = vM1;
        float sigjp = 0.0f;
        if (jp >= 0) {
            sigjp = s_sigjp;
            const float v1 = (vM1 - smin) + 1.0f;
            const float pv = (1.0f - phiv) * ((sigjp - smin) + 1.0f);
            if (pv > v1 || (pv == v1 && jp < M1)) { jstar = jp; sj = sigjp; }
        }

        // Speculative coalesced prefetches (consumed next step / at store)
        const float4* wr =
            (const float4*)((const char*)g_WbT + (unsigned)jstar * (unsigned)(MN_ * 4));
        c0 = wr[ft]; c1 = wr[400+ft]; c2 = wr[800+ft]; c3 = wr[1200+ft];
        const int gcol = jstar >> 3;
        const float wd0 = g_WdT[gcol * D_IN + tid];
        const float wd1 = (tid < D_IN - 416) ? g_WdT[gcol * D_IN + tid + 416] : 0.f;

        if (tid == 0) s_tt = tanhf(sj);      // scalarized; read after bar2

        // Rank of q among lam (stable top-k), pi-space
        const int q  = (int)((unsigned)jstar % 800u);
        const int gp = jp >> 3;              // meaningful only when jp>=0
        float pvp = 0.0f;
        if (jp >= 0) pvp = (1.0f - phiv) * ((sigjp - smin) + 1.0f);
        float lamq = (lam_s[q] - smin) + 1.0f;
        if (jp >= 0 && q == gp) lamq = fmaxf(lamq, pvp);
        int f = 0;
        if (act) {
            const int mA = 2 * tid, mB = 2 * tid + 1;
            if (mA != q) {
                float lm = (gmA - smin) + 1.0f;
                if (jp >= 0 && mA == gp) lm = fmaxf(lm, pvp);
                f += (lm > lamq) || (lm == lamq && mA < q);
            }
            if (mB != q) {
                float lm = (gmB - smin) + 1.0f;
                if (jp >= 0 && mB == gp) lm = fmaxf(lm, pvp);
                f += (lm > lamq) || (lm == lamq && mB < q);
            }
        }
        const int cw = __reduce_add_sync(0xFFFFFFFFu, f);
        if (lane == 0) red_c[wid] = cw;
        __syncthreads();                                       // bar2
        const int cnt = __reduce_add_sync(0xFFFFFFFFu, v13 ? red_c[lane] : 0);

        // Winner iff rank < K and tanh positive (tanh>0 <=> sj>0)
        const bool win = (cnt < K_) && (sj > 0.0f);
        const float yv = win ? s_tt : 0.0f;

        wdP0 = wd0; wdP1 = wd1; gvalP = yv;
        if (win) {
            jp = jstar; phiv = yv;
        } else {
            jp = -1; phiv = 0.0f;
            c0 = make_float4(0,0,0,0); c1 = make_float4(0,0,0,0);
            c2 = make_float4(0,0,0,0); c3 = make_float4(0,0,0,0);
        }
        a0 = n0; a1 = n1; a2 = n2; a3 = n3;
    }

    // Final deferred store (t = T_BATCH-1)
    out[(T_BATCH-1) * D_IN + tid] =
        (gvalP > 0.f) ? fmaf(wdP0, gvalP, bdv0) : bdv0;
    if (tid < D_IN - 416)
        out[(T_BATCH-1) * D_IN + tid + 416] =
            (gvalP > 0.f) ? fmaf(wdP1, gvalP, bdv1) : bdv1;

    // Final outputs: x_b (exactly one-hot 1.0), phi, psis[-1]
    if (tid == 0 && jp >= 0) {
        out[T_BATCH * D_IN + jp]           = 1.0f;   // x_b
        out[T_BATCH * D_IN + MN_ + jp]     = phiv;   // phi
        out[T_BATCH * D_IN + 2 * MN_ + jp] = phiv;   // psis[-1]
    }
}

// ---------------------------------------------------------------------------
extern "C" void kernel_launch(void* const* d_in, const int* in_sizes, int n_in,
                              void* d_out, int out_size) {
    const float* X  = (const float*)d_in[0];
    const float* Wa = (const float*)d_in[1];
    const float* ba = (const float*)d_in[2];
    const float* Wb = (const float*)d_in[3];
    const float* bb = (const float*)d_in[4];
    const float* Wd = (const float*)d_in[5];
    const float* bd = (const float*)d_in[6];
    float* out = (float*)d_out;

    prep_kernel<<<PREP_BLKS, 256>>>(X, Wa, ba, Wd, Wb, bb);
    scan_kernel<<<1, 416>>>(bd, out);
}